// round 13
// baseline (speedup 1.0000x reference)
#include <cuda_runtime.h>
#include <stdint.h>

#define BB   8
#define CC   11
#define HH   512
#define WWID 512
#define NIMG (BB*CC)        // 88
#define WPR  16             // 32-bit words per row (512/32)
#define WPI  (HH*WPR)       // words per image = 8192
#define NLOSS1 512
#define NQUADS 524288
#define QPB    5958         // ceil(524288/88)

// scratch (static __device__ — no allocations)
__device__ uint32_t g_strong[NIMG*WPI];
__device__ uint32_t g_weak  [NIMG*WPI];
__device__ uint32_t g_dil   [NIMG*WPI];
__device__ float    g_t     [BB*HH*WWID];
__device__ float    g_p1[NLOSS1];
__device__ float    g_p2[NIMG];
__device__ unsigned lossmain_done = 0;
__device__ unsigned flood_done = 0;
__device__ unsigned le_count = 0;

__device__ __forceinline__ int reflectI(int r) {
    r = (r < 0) ? -r : r;
    return (r > HH-1) ? (2*(HH-1) - r) : r;
}

__device__ __forceinline__ float tf32r(float x) {
    uint32_t u = __float_as_uint(x);
    u += 0x1000u;
    u &= 0xFFFFE000u;
    return __uint_as_float(u);
}
__device__ __forceinline__ uint64_t tf32r2(uint64_t x) {
    uint32_t lo = (uint32_t)x, hi = (uint32_t)(x >> 32);
    lo = (lo + 0x1000u) & 0xFFFFE000u;
    hi = (hi + 0x1000u) & 0xFFFFE000u;
    return ((uint64_t)hi << 32) | lo;
}

__device__ __forceinline__ uint64_t fma2(uint64_t a, uint64_t b, uint64_t c) {
    uint64_t d; asm("fma.rn.f32x2 %0,%1,%2,%3;" : "=l"(d) : "l"(a), "l"(b), "l"(c)); return d;
}
__device__ __forceinline__ uint64_t mul2(uint64_t a, uint64_t b) {
    uint64_t d; asm("mul.rn.f32x2 %0,%1,%2;" : "=l"(d) : "l"(a), "l"(b)); return d;
}
__device__ __forceinline__ uint64_t add2(uint64_t a, uint64_t b) {
    uint64_t d; asm("add.rn.f32x2 %0,%1,%2;" : "=l"(d) : "l"(a), "l"(b)); return d;
}
__device__ __forceinline__ uint64_t sub2(uint64_t a, uint64_t b) {
    uint64_t d; asm("sub.rn.f32x2 %0,%1,%2;" : "=l"(d) : "l"(a), "l"(b)); return d;
}
__device__ __forceinline__ uint64_t pack2(float lo, float hi) {
    return ((uint64_t)__float_as_uint(hi) << 32) | (uint64_t)__float_as_uint(lo);
}

// ---------------------------------------------------------------------------
// Kernel 1: edges (R10 structure: static smem, dir packed in mag low bits)
// + patt0/patt1 cached in registers across the 6-pair loop.
// Arithmetic chains bit-identical to R10.
// ---------------------------------------------------------------------------
__global__ void __launch_bounds__(512, 4) edges_kernel(const int* __restrict__ gt)
{
    __shared__ __align__(16) uint64_t s_patt[1440];   // 36*40
    __shared__ __align__(16) uint64_t s_v   [1440];   // 36*40
    __shared__ __align__(16) uint64_t s_b   [1296];   // 36*36
    __shared__ __align__(16) uint64_t s_mag [1156];   // 34*34 (dir in low bits)
    __shared__ uint8_t  s_gt[1600];                   // 40*40

    const int b    = blockIdx.z;
    const int x0   = blockIdx.x * 32;
    const int y0   = blockIdx.y * 32;
    const int tid  = threadIdx.x;
    const int lane = tid & 31;
    const bool interior = (blockIdx.x != 0) && (blockIdx.x != 15)
                       && (blockIdx.y != 0) && (blockIdx.y != 15);

    const float G0 = tf32r(0.054488684549642945f);
    const float G1 = tf32r(0.244201342003233320f);
    const float G2 = tf32r(0.402619946894227900f);
    const uint64_t G0p = pack2(G0, G0), G1p = pack2(G1, G1), G2p = pack2(G2, G2);
    const uint64_t M2p = pack2(-2.f, -2.f), P2p = pack2(2.f, 2.f);
    const uint64_t Z2  = 0;
    const float TT = 0.41421356237309503f;

    float lutv;
    {
        float a0 = (float)( lane       & 1);
        float a1 = (float)((lane >> 1) & 1);
        float a2 = (float)((lane >> 2) & 1);
        float a3 = (float)((lane >> 3) & 1);
        float a4 = (float)((lane >> 4) & 1);
        float s = G0 * a0;
        s = fmaf(G1, a1, s);
        s = fmaf(G2, a2, s);
        s = fmaf(G1, a3, s);
        s = fmaf(G0, a4, s);
        lutv = tf32r(s);
    }

    for (int e = tid; e < 1600; e += 512) {
        int i = e / 40, j = e - 40*i;
        s_gt[e] = (uint8_t)gt[(b << 18) + (reflectI(y0-4+i) << 9) + reflectI(x0-4+j)];
    }
    __syncthreads();

    for (int e = tid; e < 1440; e += 512) {
        int i = e / 40, j = e - 40*i;
        uint64_t B = 0;
        #pragma unroll
        for (int k = 0; k < 5; k++) {
            int g = s_gt[(i+k)*40 + j];
            B |= 1ull << (5*g + k);
        }
        s_patt[e] = B;
    }
    __syncthreads();

    // class-invariant register caches (R7-proven to fit in 32 regs)
    const uint64_t patt0 = s_patt[tid];
    const uint64_t patt1 = s_patt[tid + 512];

    const int sb_i0 = tid / 34;
    const int sb_base0 = sb_i0*36 + (tid - 34*sb_i0) + 37;
    const int sb_i1 = (tid + 512) / 34;
    const int sb_base1 = sb_i1*36 + ((tid + 512) - 34*sb_i1) + 37;

    auto sobel_math = [&](uint64_t b00, uint64_t b01, uint64_t b02,
                          uint64_t b10, uint64_t b12,
                          uint64_t b20, uint64_t b21, uint64_t b22) -> uint64_t {
        uint64_t gxp = sub2(Z2, b00);
        gxp = add2(gxp, b02);
        gxp = fma2(M2p, b10, gxp);
        gxp = fma2(P2p, b12, gxp);
        gxp = sub2(gxp, b20);
        gxp = add2(gxp, b22);
        uint64_t gyp = sub2(Z2, b00);
        gyp = fma2(M2p, b01, gyp);
        gyp = sub2(gyp, b02);
        gyp = add2(gyp, b20);
        gyp = fma2(P2p, b21, gyp);
        gyp = add2(gyp, b22);

        float gx0 = __uint_as_float((uint32_t)gxp);
        float gx1 = __uint_as_float((uint32_t)(gxp >> 32));
        float gy0 = __uint_as_float((uint32_t)gyp);
        float gy1 = __uint_as_float((uint32_t)(gyp >> 32));

        float s20 = __fadd_rn(__fadd_rn(__fmul_rn(gx0,gx0), __fmul_rn(gy0,gy0)), 1e-6f);
        float s21 = __fadd_rn(__fadd_rn(__fmul_rn(gx1,gx1), __fmul_rn(gy1,gy1)), 1e-6f);
        float m0 = sqrtf(s20);
        float m1 = sqrtf(s21);
        float ax0 = fabsf(gx0), ay0 = fabsf(gy0);
        float ax1 = fabsf(gx1), ay1 = fabsf(gy1);
        uint32_t d0 = (ay0 <= TT*ax0) ? 0u
                    : (ax0 <= TT*ay0) ? 1u
                    : (((gx0 > 0.f) == (gy0 > 0.f)) ? 2u : 3u);
        uint32_t d1 = (ay1 <= TT*ax1) ? 0u
                    : (ax1 <= TT*ay1) ? 1u
                    : (((gx1 > 0.f) == (gy1 > 0.f)) ? 2u : 3u);
        uint32_t mb0 = (__float_as_uint(m0) & ~3u) | d0;
        uint32_t mb1 = (__float_as_uint(m1) & ~3u) | d1;
        return ((uint64_t)mb1 << 32) | mb0;
    };

    auto sobel_fast = [&](int e, int base) {
        s_mag[e] = sobel_math(s_b[base-37], s_b[base-36], s_b[base-35],
                              s_b[base-1],                s_b[base+1],
                              s_b[base+35], s_b[base+36], s_b[base+37]);
    };

    const int nw  = tid >> 5;
    const int nmj = lane + 1;

    #pragma unroll 1
    for (int c2 = 0; c2 < 6; c2++) {
        const int sh0 = 10*c2, sh1 = sh0 + 5;

        // vertical blur via LUT; patt0/patt1 from registers, third slice from smem
        {
            float v0 = __shfl_sync(0xffffffffu, lutv, (int)((patt0 >> sh0) & 31));
            float v1 = __shfl_sync(0xffffffffu, lutv, (int)((patt0 >> sh1) & 31));
            s_v[tid] = pack2(v0, v1);
            v0 = __shfl_sync(0xffffffffu, lutv, (int)((patt1 >> sh0) & 31));
            v1 = __shfl_sync(0xffffffffu, lutv, (int)((patt1 >> sh1) & 31));
            s_v[tid + 512] = pack2(v0, v1);
            if (tid < 416) {                 // warps 0..12 fully active (shfl-safe)
                uint64_t B = s_patt[tid + 1024];
                v0 = __shfl_sync(0xffffffffu, lutv, (int)((B >> sh0) & 31));
                v1 = __shfl_sync(0xffffffffu, lutv, (int)((B >> sh1) & 31));
                s_v[tid + 1024] = pack2(v0, v1);
            }
        }
        __syncthreads();

        for (int e = tid; e < 1296; e += 512) {
            int i = e / 36, j = e - 36*i;
            const uint64_t* row = s_v + i*40 + j;
            uint64_t s = mul2(G0p, row[0]);
            s = fma2(G1p, row[1], s);
            s = fma2(G2p, row[2], s);
            s = fma2(G1p, row[3], s);
            s = fma2(G0p, row[4], s);
            s_b[e] = tf32r2(s);
        }
        __syncthreads();

        if (interior) {
            sobel_fast(tid,       sb_base0);
            sobel_fast(tid + 512, sb_base1);
            if (tid < 132) {
                int e = tid + 1024;
                int i = e / 34;
                sobel_fast(e, i*36 + (e - 34*i) + 37);
            }
        } else {
            for (int e = tid; e < 1156; e += 512) {
                int i = e / 34, j = e - 34*i;
                int gy = y0 - 1 + i, gx = x0 - 1 + j;
                uint64_t magp = 0;
                if ((unsigned)gy < (unsigned)HH && (unsigned)gx < (unsigned)WWID) {
                    int am = (max(gy-1, 0)      - (y0 - 2)) * 36;
                    int a0 = (gy                - (y0 - 2)) * 36;
                    int ap = (min(gy+1, HH-1)   - (y0 - 2)) * 36;
                    int cm =  max(gx-1, 0)      - (x0 - 2);
                    int c0 =  gx                - (x0 - 2);
                    int cp =  min(gx+1, WWID-1) - (x0 - 2);
                    magp = sobel_math(s_b[am+cm], s_b[am+c0], s_b[am+cp],
                                      s_b[a0+cm],             s_b[a0+cp],
                                      s_b[ap+cm], s_b[ap+c0], s_b[ap+cp]);
                }
                s_mag[e] = magp;
            }
        }
        __syncthreads();

        {
            const float* magf = (const float*)s_mag;
            #pragma unroll
            for (int t = 0; t < 2; t++) {
                int r  = nw + t*16;
                int mi = r + 1;
                uint64_t mp = s_mag[mi*34 + nmj];
                unsigned sbits[2], wbits[2];
                #pragma unroll
                for (int l = 0; l < 2; l++) {
                    uint32_t mb = (uint32_t)(l ? (mp >> 32) : mp);
                    float m = __uint_as_float(mb);
                    int d = (int)(mb & 3u);
                    int dy = (d == 0) ? 0 : ((d == 2) ? -1 : 1);
                    int dx = (d == 1) ? 0 : 1;
                    float m1 = magf[((mi+dy)*34 + (nmj+dx))*2 + l];
                    float m2 = magf[((mi-dy)*34 + (nmj-dx))*2 + l];
                    float mr = tf32r(m);
                    int e2 = 0;
                    if (mr > tf32r(m1) && mr > tf32r(m2))
                        e2 = (m > 0.2f) ? 2 : ((m > 0.1f) ? 1 : 0);
                    sbits[l] = __ballot_sync(0xffffffffu, e2 == 2);
                    wbits[l] = __ballot_sync(0xffffffffu, e2 == 1);
                }
                if (lane == 0) {
                    int c = 2*c2;
                    int base0 = ((b*CC + c)*HH + y0 + r)*WPR + blockIdx.x;
                    g_strong[base0] = sbits[0];
                    g_weak[base0]   = wbits[0];
                    if (c + 1 < CC) {
                        int base1 = base0 + HH*WPR;
                        g_strong[base1] = sbits[1];
                        g_weak[base1]   = wbits[1];
                    }
                }
            }
        }
        __syncthreads();
    }
}

// ---------------------------------------------------------------------------
// Kernel 2: flood (blocks 0..87) + loss-main (blocks 88..599) + fused
// loss_edge tail executed by the 88 flood blocks after both phases complete.
// Only flood blocks spin (all co-resident in wave 1) -> no deadlock.
// ---------------------------------------------------------------------------
__global__ void __launch_bounds__(1024) flood_loss_kernel(
    const float* __restrict__ pd,
    const int*   __restrict__ gt,
    const float* __restrict__ weight,
    float* __restrict__ out)
{
    extern __shared__ uint32_t sh[];
    const int tid = threadIdx.x;
    const int lane = tid & 31;

    if (blockIdx.x >= NIMG) {
        // ------------------ loss-main: t = w[g]*(vg - lse) ------------------
        const int lbid = blockIdx.x - NIMG;
        const int q    = lbid * 1024 + tid;
        const int b    = q >> 16;
        const int hwq  = q & 65535;

        const int4 g4 = ((const int4*)gt)[q];
        const float4* base = (const float4*)pd + (((size_t)b * CC) << 16) + hwq;
        float4 vals[CC];
        #pragma unroll
        for (int c = 0; c < CC; c++) vals[c] = base[(size_t)c << 16];

        float4 tq;
        float acc = 0.f;
        const int gs[4] = {g4.x, g4.y, g4.z, g4.w};
        #pragma unroll
        for (int j = 0; j < 4; j++) {
            int g = gs[j];
            float vmax = -1e30f, vg = 0.f;
            #pragma unroll
            for (int c = 0; c < CC; c++) {
                float v = (j == 0) ? vals[c].x : (j == 1) ? vals[c].y
                        : (j == 2) ? vals[c].z : vals[c].w;
                if (c == g) vg = v;
                vmax = fmaxf(vmax, v);
            }
            float s = 0.f;
            #pragma unroll
            for (int c = 0; c < CC; c++) {
                float v = (j == 0) ? vals[c].x : (j == 1) ? vals[c].y
                        : (j == 2) ? vals[c].z : vals[c].w;
                s += __expf(v - vmax);
            }
            float lse = vmax + __logf(s);
            float t = weight[g] * (vg - lse);
            ((float*)&tq)[j] = t;
            acc += t;
        }
        ((float4*)g_t)[q] = tq;

        #pragma unroll
        for (int off = 16; off > 0; off >>= 1)
            acc += __shfl_down_sync(0xffffffffu, acc, off);
        float* ws = (float*)sh;
        if (lane == 0) ws[tid >> 5] = acc;
        __syncthreads();
        if (tid == 0) {
            float t = 0.f;
            #pragma unroll
            for (int i = 0; i < 32; i++) t += ws[i];
            g_p1[lbid] = t;
            __threadfence();
            atomicAdd(&lossmain_done, 1u);
        }
        return;
    }

    // ------------------------------- flood ---------------------------------
    uint32_t* sS = sh;
    uint32_t* sW = sh + WPI;

    const int img = blockIdx.x;
    const uint32_t* gsb = g_strong + (size_t)img * WPI;
    const uint32_t* gwb = g_weak   + (size_t)img * WPI;

    for (int i = tid; i < WPI; i += 1024) {
        uint32_t s = gsb[i];
        sS[i] = s;
        sW[i] = gwb[i] & ~s;
    }
    __syncthreads();

    const int col = tid & 15;
    const int r0  = (tid >> 4) * 8;

    for (;;) {
        bool ch = false;
        #pragma unroll
        for (int pass = 0; pass < 2; pass++) {
            for (int kk = 0; kk < 8; kk++) {
                int k = pass ? 7 - kk : kk;
                int r = r0 + k;
                int i = r * WPR + col;
                uint32_t w = sW[i];
                if (!w) continue;
                uint32_t ext = 0;
                if (r > 0)     ext |= sS[i - WPR];
                if (r < HH-1)  ext |= sS[i + WPR];
                uint32_t side = 0;
                if (col > 0) {
                    uint32_t lo = sS[i-1];
                    if (r > 0)    lo |= sS[i-1-WPR];
                    if (r < HH-1) lo |= sS[i-1+WPR];
                    side |= lo >> 31;
                }
                if (col < WPR-1) {
                    uint32_t hi = sS[i+1];
                    if (r > 0)    hi |= sS[i+1-WPR];
                    if (r < HH-1) hi |= sS[i+1+WPR];
                    side |= hi << 31;
                }
                uint32_t cur = sS[i];
                bool lch = false;
                for (;;) {
                    uint32_t o = cur | ext;
                    uint32_t d = o | (o << 1) | (o >> 1) | side;
                    uint32_t cand = d & w;
                    if (!cand) break;
                    cur |= cand; w &= ~cand; lch = true;
                }
                if (lch) { sS[i] = cur; sW[i] = w; ch = true; }
            }
        }
        if (!__syncthreads_or((int)ch)) break;
    }

    uint32_t* gd = g_dil + (size_t)img * WPI;
    #pragma unroll
    for (int k = 0; k < 8; k++) {
        int r = r0 + k;
        int i = r * WPR + col;
        uint32_t s = sS[i];
        uint32_t d = s | (s << 1) | (s >> 1);
        if (r > 0)       d |= sS[i - WPR];
        if (r < HH-1)    d |= sS[i + WPR];
        if (col > 0)     d |= sS[i-1] >> 31;
        if (col < WPR-1) d |= sS[i+1] << 31;
        gd[i] = d;
    }

    __threadfence();
    __syncthreads();
    if (tid == 0) {
        atomicAdd(&flood_done, 1u);
        while (atomicAdd(&flood_done, 0u) < (unsigned)NIMG ||
               atomicAdd(&lossmain_done, 0u) < (unsigned)NLOSS1)
            __nanosleep(64);
    }
    __syncthreads();

    // --------------------------- loss-edge tail -----------------------------
    const int q0   = img * QPB;
    const int qend = min(q0 + QPB, NQUADS);
    float s2 = 0.f;
    for (int q = q0 + tid; q < qend; q += 1024) {
        const int b  = q >> 16;
        const int hw = (q & 65535) << 2;
        const int widx = hw >> 5;
        const int4   g4 = ((const int4*)gt)[q];
        const float4 t4 = ((const float4*)g_t)[q];
        const int   gsx[4] = {g4.x, g4.y, g4.z, g4.w};
        const float tsx[4] = {t4.x, t4.y, t4.z, t4.w};
        #pragma unroll
        for (int j = 0; j < 4; j++) {
            uint32_t bits = g_dil[(size_t)(b * CC + gsx[j]) * WPI + widx];
            if ((bits >> ((hw + j) & 31)) & 1u) s2 += tsx[j];
        }
    }
    #pragma unroll
    for (int off = 16; off > 0; off >>= 1)
        s2 += __shfl_down_sync(0xffffffffu, s2, off);
    float* ws = (float*)sh;
    if (lane == 0) ws[tid >> 5] = s2;
    __syncthreads();
    __shared__ bool isLast;
    if (tid == 0) {
        float t = 0.f;
        #pragma unroll
        for (int i = 0; i < 32; i++) t += ws[i];
        g_p2[img] = t;
        __threadfence();
        unsigned v = atomicAdd(&le_count, 1u);
        isLast = (v == NIMG - 1);
    }
    __syncthreads();

    if (isLast) {
        double a = 0.0;
        for (int i = tid; i < NLOSS1; i += 1024) a += (double)g_p1[i];
        for (int i = tid; i < NIMG;   i += 1024) a += 2.0 * (double)g_p2[i];
        #pragma unroll
        for (int off = 16; off > 0; off >>= 1)
            a += __shfl_down_sync(0xffffffffu, a, off);
        double* wd = (double*)sh;
        if (lane == 0) wd[tid >> 5] = a;
        __syncthreads();
        if (tid == 0) {
            double t = 0.0;
            #pragma unroll
            for (int i = 0; i < 32; i++) t += wd[i];
            out[0] = (float)(-t / 2097152.0);
            lossmain_done = 0;
            flood_done = 0;
            le_count = 0;
        }
    }
}

// ---------------------------------------------------------------------------
extern "C" void kernel_launch(void* const* d_in, const int* in_sizes, int n_in,
                              void* d_out, int out_size)
{
    (void)in_sizes; (void)n_in; (void)out_size;
    const float* pd     = (const float*)d_in[0];
    const int*   gt     = (const int*)  d_in[1];
    const float* weight = (const float*)d_in[2];
    float* out = (float*)d_out;

    cudaFuncSetAttribute(flood_loss_kernel,
                         cudaFuncAttributeMaxDynamicSharedMemorySize, 2 * WPI * 4);

    dim3 eg(16, 16, BB);
    edges_kernel<<<eg, 512>>>(gt);
    flood_loss_kernel<<<NIMG + NLOSS1, 1024, 2 * WPI * 4>>>(pd, gt, weight, out);
}

// round 14
// speedup vs baseline: 1.0900x; 1.0900x over previous
#include <cuda_runtime.h>
#include <stdint.h>

#define BB   8
#define CC   11
#define HH   512
#define WWID 512
#define NIMG (BB*CC)        // 88
#define WPR  16             // 32-bit words per row (512/32)
#define WPI  (HH*WPR)       // words per image = 8192
#define NLOSS1 512
#define NLOSS2 2048

// scratch (static __device__ — no allocations)
__device__ uint32_t g_strong[NIMG*WPI];
__device__ uint32_t g_weak  [NIMG*WPI];
__device__ uint32_t g_dil   [NIMG*WPI];
__device__ float    g_t     [BB*HH*WWID];
__device__ float    g_p1[NLOSS1];
__device__ float    g_p2[NLOSS2];
__device__ unsigned g_count = 0;

__device__ __forceinline__ int reflectI(int r) {
    r = (r < 0) ? -r : r;
    return (r > HH-1) ? (2*(HH-1) - r) : r;
}

__device__ __forceinline__ float tf32r(float x) {
    uint32_t u = __float_as_uint(x);
    u += 0x1000u;
    u &= 0xFFFFE000u;
    return __uint_as_float(u);
}
__device__ __forceinline__ uint64_t tf32r2(uint64_t x) {
    uint32_t lo = (uint32_t)x, hi = (uint32_t)(x >> 32);
    lo = (lo + 0x1000u) & 0xFFFFE000u;
    hi = (hi + 0x1000u) & 0xFFFFE000u;
    return ((uint64_t)hi << 32) | lo;
}

__device__ __forceinline__ uint64_t fma2(uint64_t a, uint64_t b, uint64_t c) {
    uint64_t d; asm("fma.rn.f32x2 %0,%1,%2,%3;" : "=l"(d) : "l"(a), "l"(b), "l"(c)); return d;
}
__device__ __forceinline__ uint64_t mul2(uint64_t a, uint64_t b) {
    uint64_t d; asm("mul.rn.f32x2 %0,%1,%2;" : "=l"(d) : "l"(a), "l"(b)); return d;
}
__device__ __forceinline__ uint64_t add2(uint64_t a, uint64_t b) {
    uint64_t d; asm("add.rn.f32x2 %0,%1,%2;" : "=l"(d) : "l"(a), "l"(b)); return d;
}
__device__ __forceinline__ uint64_t sub2(uint64_t a, uint64_t b) {
    uint64_t d; asm("sub.rn.f32x2 %0,%1,%2;" : "=l"(d) : "l"(a), "l"(b)); return d;
}
__device__ __forceinline__ uint64_t pack2(float lo, float hi) {
    return ((uint64_t)__float_as_uint(hi) << 32) | (uint64_t)__float_as_uint(lo);
}

// ---------------------------------------------------------------------------
// Kernel 1: edges (R10 structure: static smem, dir packed in mag low bits)
// + patt0/patt1 cached in registers across the 6-pair loop.
// Arithmetic chains bit-identical to R10.
// ---------------------------------------------------------------------------
__global__ void __launch_bounds__(512, 4) edges_kernel(const int* __restrict__ gt)
{
    __shared__ __align__(16) uint64_t s_patt[1440];   // 36*40
    __shared__ __align__(16) uint64_t s_v   [1440];   // 36*40
    __shared__ __align__(16) uint64_t s_b   [1296];   // 36*36
    __shared__ __align__(16) uint64_t s_mag [1156];   // 34*34 (dir in low bits)
    __shared__ uint8_t  s_gt[1600];                   // 40*40

    const int b    = blockIdx.z;
    const int x0   = blockIdx.x * 32;
    const int y0   = blockIdx.y * 32;
    const int tid  = threadIdx.x;
    const int lane = tid & 31;
    const bool interior = (blockIdx.x != 0) && (blockIdx.x != 15)
                       && (blockIdx.y != 0) && (blockIdx.y != 15);

    const float G0 = tf32r(0.054488684549642945f);
    const float G1 = tf32r(0.244201342003233320f);
    const float G2 = tf32r(0.402619946894227900f);
    const uint64_t G0p = pack2(G0, G0), G1p = pack2(G1, G1), G2p = pack2(G2, G2);
    const uint64_t M2p = pack2(-2.f, -2.f), P2p = pack2(2.f, 2.f);
    const uint64_t Z2  = 0;
    const float TT = 0.41421356237309503f;

    float lutv;
    {
        float a0 = (float)( lane       & 1);
        float a1 = (float)((lane >> 1) & 1);
        float a2 = (float)((lane >> 2) & 1);
        float a3 = (float)((lane >> 3) & 1);
        float a4 = (float)((lane >> 4) & 1);
        float s = G0 * a0;
        s = fmaf(G1, a1, s);
        s = fmaf(G2, a2, s);
        s = fmaf(G1, a3, s);
        s = fmaf(G0, a4, s);
        lutv = tf32r(s);
    }

    for (int e = tid; e < 1600; e += 512) {
        int i = e / 40, j = e - 40*i;
        s_gt[e] = (uint8_t)gt[(b << 18) + (reflectI(y0-4+i) << 9) + reflectI(x0-4+j)];
    }
    __syncthreads();

    for (int e = tid; e < 1440; e += 512) {
        int i = e / 40, j = e - 40*i;
        uint64_t B = 0;
        #pragma unroll
        for (int k = 0; k < 5; k++) {
            int g = s_gt[(i+k)*40 + j];
            B |= 1ull << (5*g + k);
        }
        s_patt[e] = B;
    }
    __syncthreads();

    // class-invariant register caches
    const uint64_t patt0 = s_patt[tid];
    const uint64_t patt1 = s_patt[tid + 512];

    const int sb_i0 = tid / 34;
    const int sb_base0 = sb_i0*36 + (tid - 34*sb_i0) + 37;
    const int sb_i1 = (tid + 512) / 34;
    const int sb_base1 = sb_i1*36 + ((tid + 512) - 34*sb_i1) + 37;

    auto sobel_math = [&](uint64_t b00, uint64_t b01, uint64_t b02,
                          uint64_t b10, uint64_t b12,
                          uint64_t b20, uint64_t b21, uint64_t b22) -> uint64_t {
        uint64_t gxp = sub2(Z2, b00);
        gxp = add2(gxp, b02);
        gxp = fma2(M2p, b10, gxp);
        gxp = fma2(P2p, b12, gxp);
        gxp = sub2(gxp, b20);
        gxp = add2(gxp, b22);
        uint64_t gyp = sub2(Z2, b00);
        gyp = fma2(M2p, b01, gyp);
        gyp = sub2(gyp, b02);
        gyp = add2(gyp, b20);
        gyp = fma2(P2p, b21, gyp);
        gyp = add2(gyp, b22);

        float gx0 = __uint_as_float((uint32_t)gxp);
        float gx1 = __uint_as_float((uint32_t)(gxp >> 32));
        float gy0 = __uint_as_float((uint32_t)gyp);
        float gy1 = __uint_as_float((uint32_t)(gyp >> 32));

        float s20 = __fadd_rn(__fadd_rn(__fmul_rn(gx0,gx0), __fmul_rn(gy0,gy0)), 1e-6f);
        float s21 = __fadd_rn(__fadd_rn(__fmul_rn(gx1,gx1), __fmul_rn(gy1,gy1)), 1e-6f);
        float m0 = sqrtf(s20);
        float m1 = sqrtf(s21);
        float ax0 = fabsf(gx0), ay0 = fabsf(gy0);
        float ax1 = fabsf(gx1), ay1 = fabsf(gy1);
        uint32_t d0 = (ay0 <= TT*ax0) ? 0u
                    : (ax0 <= TT*ay0) ? 1u
                    : (((gx0 > 0.f) == (gy0 > 0.f)) ? 2u : 3u);
        uint32_t d1 = (ay1 <= TT*ax1) ? 0u
                    : (ax1 <= TT*ay1) ? 1u
                    : (((gx1 > 0.f) == (gy1 > 0.f)) ? 2u : 3u);
        uint32_t mb0 = (__float_as_uint(m0) & ~3u) | d0;
        uint32_t mb1 = (__float_as_uint(m1) & ~3u) | d1;
        return ((uint64_t)mb1 << 32) | mb0;
    };

    auto sobel_fast = [&](int e, int base) {
        s_mag[e] = sobel_math(s_b[base-37], s_b[base-36], s_b[base-35],
                              s_b[base-1],                s_b[base+1],
                              s_b[base+35], s_b[base+36], s_b[base+37]);
    };

    const int nw  = tid >> 5;
    const int nmj = lane + 1;

    #pragma unroll 1
    for (int c2 = 0; c2 < 6; c2++) {
        const int sh0 = 10*c2, sh1 = sh0 + 5;

        // vertical blur via LUT; patt0/patt1 from registers, third slice from smem
        {
            float v0 = __shfl_sync(0xffffffffu, lutv, (int)((patt0 >> sh0) & 31));
            float v1 = __shfl_sync(0xffffffffu, lutv, (int)((patt0 >> sh1) & 31));
            s_v[tid] = pack2(v0, v1);
            v0 = __shfl_sync(0xffffffffu, lutv, (int)((patt1 >> sh0) & 31));
            v1 = __shfl_sync(0xffffffffu, lutv, (int)((patt1 >> sh1) & 31));
            s_v[tid + 512] = pack2(v0, v1);
            if (tid < 416) {                 // warps 0..12 fully active (shfl-safe)
                uint64_t B = s_patt[tid + 1024];
                v0 = __shfl_sync(0xffffffffu, lutv, (int)((B >> sh0) & 31));
                v1 = __shfl_sync(0xffffffffu, lutv, (int)((B >> sh1) & 31));
                s_v[tid + 1024] = pack2(v0, v1);
            }
        }
        __syncthreads();

        for (int e = tid; e < 1296; e += 512) {
            int i = e / 36, j = e - 36*i;
            const uint64_t* row = s_v + i*40 + j;
            uint64_t s = mul2(G0p, row[0]);
            s = fma2(G1p, row[1], s);
            s = fma2(G2p, row[2], s);
            s = fma2(G1p, row[3], s);
            s = fma2(G0p, row[4], s);
            s_b[e] = tf32r2(s);
        }
        __syncthreads();

        if (interior) {
            sobel_fast(tid,       sb_base0);
            sobel_fast(tid + 512, sb_base1);
            if (tid < 132) {
                int e = tid + 1024;
                int i = e / 34;
                sobel_fast(e, i*36 + (e - 34*i) + 37);
            }
        } else {
            for (int e = tid; e < 1156; e += 512) {
                int i = e / 34, j = e - 34*i;
                int gy = y0 - 1 + i, gx = x0 - 1 + j;
                uint64_t magp = 0;
                if ((unsigned)gy < (unsigned)HH && (unsigned)gx < (unsigned)WWID) {
                    int am = (max(gy-1, 0)      - (y0 - 2)) * 36;
                    int a0 = (gy                - (y0 - 2)) * 36;
                    int ap = (min(gy+1, HH-1)   - (y0 - 2)) * 36;
                    int cm =  max(gx-1, 0)      - (x0 - 2);
                    int c0 =  gx                - (x0 - 2);
                    int cp =  min(gx+1, WWID-1) - (x0 - 2);
                    magp = sobel_math(s_b[am+cm], s_b[am+c0], s_b[am+cp],
                                      s_b[a0+cm],             s_b[a0+cp],
                                      s_b[ap+cm], s_b[ap+c0], s_b[ap+cp]);
                }
                s_mag[e] = magp;
            }
        }
        __syncthreads();

        {
            const float* magf = (const float*)s_mag;
            #pragma unroll
            for (int t = 0; t < 2; t++) {
                int r  = nw + t*16;
                int mi = r + 1;
                uint64_t mp = s_mag[mi*34 + nmj];
                unsigned sbits[2], wbits[2];
                #pragma unroll
                for (int l = 0; l < 2; l++) {
                    uint32_t mb = (uint32_t)(l ? (mp >> 32) : mp);
                    float m = __uint_as_float(mb);
                    int d = (int)(mb & 3u);
                    int dy = (d == 0) ? 0 : ((d == 2) ? -1 : 1);
                    int dx = (d == 1) ? 0 : 1;
                    float m1 = magf[((mi+dy)*34 + (nmj+dx))*2 + l];
                    float m2 = magf[((mi-dy)*34 + (nmj-dx))*2 + l];
                    float mr = tf32r(m);
                    int e2 = 0;
                    if (mr > tf32r(m1) && mr > tf32r(m2))
                        e2 = (m > 0.2f) ? 2 : ((m > 0.1f) ? 1 : 0);
                    sbits[l] = __ballot_sync(0xffffffffu, e2 == 2);
                    wbits[l] = __ballot_sync(0xffffffffu, e2 == 1);
                }
                if (lane == 0) {
                    int c = 2*c2;
                    int base0 = ((b*CC + c)*HH + y0 + r)*WPR + blockIdx.x;
                    g_strong[base0] = sbits[0];
                    g_weak[base0]   = wbits[0];
                    if (c + 1 < CC) {
                        int base1 = base0 + HH*WPR;
                        g_strong[base1] = sbits[1];
                        g_weak[base1]   = wbits[1];
                    }
                }
            }
        }
        __syncthreads();
    }
}

// ---------------------------------------------------------------------------
// Kernel 2: fused flood (blocks 0..87) + loss-main (blocks 88..599).
// Exact R10 version (no spin, no tail -> low regs, full occupancy).
// ---------------------------------------------------------------------------
__global__ void __launch_bounds__(1024) flood_loss_kernel(
    const float* __restrict__ pd,
    const int*   __restrict__ gt,
    const float* __restrict__ weight)
{
    extern __shared__ uint32_t sh[];
    const int tid = threadIdx.x;

    if (blockIdx.x >= NIMG) {
        const int lbid = blockIdx.x - NIMG;
        const int q    = lbid * 1024 + tid;
        const int b    = q >> 16;
        const int hwq  = q & 65535;

        const int4 g4 = ((const int4*)gt)[q];
        const float4* base = (const float4*)pd + (((size_t)b * CC) << 16) + hwq;
        float4 vals[CC];
        #pragma unroll
        for (int c = 0; c < CC; c++) vals[c] = base[(size_t)c << 16];

        float4 tq;
        float acc = 0.f;
        const int gs[4] = {g4.x, g4.y, g4.z, g4.w};
        #pragma unroll
        for (int j = 0; j < 4; j++) {
            int g = gs[j];
            float vmax = -1e30f, vg = 0.f;
            #pragma unroll
            for (int c = 0; c < CC; c++) {
                float v = (j == 0) ? vals[c].x : (j == 1) ? vals[c].y
                        : (j == 2) ? vals[c].z : vals[c].w;
                if (c == g) vg = v;
                vmax = fmaxf(vmax, v);
            }
            float s = 0.f;
            #pragma unroll
            for (int c = 0; c < CC; c++) {
                float v = (j == 0) ? vals[c].x : (j == 1) ? vals[c].y
                        : (j == 2) ? vals[c].z : vals[c].w;
                s += __expf(v - vmax);
            }
            float lse = vmax + __logf(s);
            float t = weight[g] * (vg - lse);
            ((float*)&tq)[j] = t;
            acc += t;
        }
        ((float4*)g_t)[q] = tq;

        #pragma unroll
        for (int off = 16; off > 0; off >>= 1)
            acc += __shfl_down_sync(0xffffffffu, acc, off);
        float* ws = (float*)sh;
        if ((tid & 31) == 0) ws[tid >> 5] = acc;
        __syncthreads();
        if (tid == 0) {
            float t = 0.f;
            #pragma unroll
            for (int i = 0; i < 32; i++) t += ws[i];
            g_p1[lbid] = t;
        }
        return;
    }

    uint32_t* sS = sh;
    uint32_t* sW = sh + WPI;

    const int img = blockIdx.x;
    const uint32_t* gs = g_strong + (size_t)img * WPI;
    const uint32_t* gw = g_weak   + (size_t)img * WPI;

    for (int i = tid; i < WPI; i += 1024) {
        uint32_t s = gs[i];
        sS[i] = s;
        sW[i] = gw[i] & ~s;
    }
    __syncthreads();

    const int col = tid & 15;
    const int r0  = (tid >> 4) * 8;

    for (;;) {
        bool ch = false;
        #pragma unroll
        for (int pass = 0; pass < 2; pass++) {
            for (int kk = 0; kk < 8; kk++) {
                int k = pass ? 7 - kk : kk;
                int r = r0 + k;
                int i = r * WPR + col;
                uint32_t w = sW[i];
                if (!w) continue;
                uint32_t ext = 0;
                if (r > 0)     ext |= sS[i - WPR];
                if (r < HH-1)  ext |= sS[i + WPR];
                uint32_t side = 0;
                if (col > 0) {
                    uint32_t lo = sS[i-1];
                    if (r > 0)    lo |= sS[i-1-WPR];
                    if (r < HH-1) lo |= sS[i-1+WPR];
                    side |= lo >> 31;
                }
                if (col < WPR-1) {
                    uint32_t hi = sS[i+1];
                    if (r > 0)    hi |= sS[i+1-WPR];
                    if (r < HH-1) hi |= sS[i+1+WPR];
                    side |= hi << 31;
                }
                uint32_t cur = sS[i];
                bool lch = false;
                for (;;) {
                    uint32_t o = cur | ext;
                    uint32_t d = o | (o << 1) | (o >> 1) | side;
                    uint32_t cand = d & w;
                    if (!cand) break;
                    cur |= cand; w &= ~cand; lch = true;
                }
                if (lch) { sS[i] = cur; sW[i] = w; ch = true; }
            }
        }
        if (!__syncthreads_or((int)ch)) break;
    }

    uint32_t* gd = g_dil + (size_t)img * WPI;
    #pragma unroll
    for (int k = 0; k < 8; k++) {
        int r = r0 + k;
        int i = r * WPR + col;
        uint32_t s = sS[i];
        uint32_t d = s | (s << 1) | (s >> 1);
        if (r > 0)       d |= sS[i - WPR];
        if (r < HH-1)    d |= sS[i + WPR];
        if (col > 0)     d |= sS[i-1] >> 31;
        if (col < WPR-1) d |= sS[i+1] << 31;
        gd[i] = d;
    }
}

// ---------------------------------------------------------------------------
// Kernel 3: loss edge correction S2 + fused final reduction. (R10)
// ---------------------------------------------------------------------------
__global__ void __launch_bounds__(256) loss_edge_kernel(const int* __restrict__ gt,
                                                        float* __restrict__ out)
{
    const int q  = blockIdx.x * 256 + threadIdx.x;
    const int b  = q >> 16;
    const int hw = (q & 65535) << 2;
    const int widx = hw >> 5;

    const int4   g4 = ((const int4*)gt)[q];
    const float4 t4 = ((const float4*)g_t)[q];

    float s2 = 0.f;
    const int   gs[4] = {g4.x, g4.y, g4.z, g4.w};
    const float ts[4] = {t4.x, t4.y, t4.z, t4.w};
    #pragma unroll
    for (int j = 0; j < 4; j++) {
        uint32_t bits = g_dil[(size_t)(b * CC + gs[j]) * WPI + widx];
        if ((bits >> ((hw + j) & 31)) & 1u) s2 += ts[j];
    }

    #pragma unroll
    for (int off = 16; off > 0; off >>= 1)
        s2 += __shfl_down_sync(0xffffffffu, s2, off);
    __shared__ float ws[8];
    if ((threadIdx.x & 31) == 0) ws[threadIdx.x >> 5] = s2;
    __syncthreads();
    __shared__ bool isLast;
    if (threadIdx.x == 0) {
        float t = 0.f;
        #pragma unroll
        for (int i = 0; i < 8; i++) t += ws[i];
        g_p2[blockIdx.x] = t;
        __threadfence();
        unsigned v = atomicAdd(&g_count, 1u);
        isLast = (v == NLOSS2 - 1);
    }
    __syncthreads();

    if (isLast) {
        __shared__ double red[256];
        double a = 0.0;
        for (int i = threadIdx.x; i < NLOSS1; i += 256) a += (double)g_p1[i];
        for (int i = threadIdx.x; i < NLOSS2; i += 256) a += 2.0 * (double)g_p2[i];
        red[threadIdx.x] = a;
        __syncthreads();
        for (int s = 128; s > 0; s >>= 1) {
            if (threadIdx.x < s) red[threadIdx.x] += red[threadIdx.x + s];
            __syncthreads();
        }
        if (threadIdx.x == 0) {
            out[0] = (float)(-red[0] / 2097152.0);
            g_count = 0;
        }
    }
}

// ---------------------------------------------------------------------------
extern "C" void kernel_launch(void* const* d_in, const int* in_sizes, int n_in,
                              void* d_out, int out_size)
{
    (void)in_sizes; (void)n_in; (void)out_size;
    const float* pd     = (const float*)d_in[0];
    const int*   gt     = (const int*)  d_in[1];
    const float* weight = (const float*)d_in[2];
    float* out = (float*)d_out;

    cudaFuncSetAttribute(flood_loss_kernel,
                         cudaFuncAttributeMaxDynamicSharedMemorySize, 2 * WPI * 4);

    dim3 eg(16, 16, BB);
    edges_kernel<<<eg, 512>>>(gt);
    flood_loss_kernel<<<NIMG + NLOSS1, 1024, 2 * WPI * 4>>>(pd, gt, weight);
    loss_edge_kernel<<<NLOSS2, 256>>>(gt, out);
}

// round 15
// speedup vs baseline: 1.0989x; 1.0082x over previous
#include <cuda_runtime.h>
#include <stdint.h>

#define BB   8
#define CC   11
#define HH   512
#define WWID 512
#define NIMG (BB*CC)        // 88
#define WPR  16             // 32-bit words per row (512/32)
#define WPI  (HH*WPR)       // words per image = 8192
#define EDGE_BLKS 2048
#define NLOSS1 1024         // scalar loss-main blocks (512 thr, 2048 px each)
#define NLOSS2 2048

// scratch (static __device__ — no allocations)
__device__ uint32_t g_strong[NIMG*WPI];
__device__ uint32_t g_weak  [NIMG*WPI];
__device__ uint32_t g_dil   [NIMG*WPI];
__device__ float    g_t     [BB*HH*WWID];
__device__ float    g_p1[NLOSS1];
__device__ float    g_p2[NLOSS2];
__device__ unsigned g_count = 0;

__device__ __forceinline__ int reflectI(int r) {
    r = (r < 0) ? -r : r;
    return (r > HH-1) ? (2*(HH-1) - r) : r;
}

__device__ __forceinline__ float tf32r(float x) {
    uint32_t u = __float_as_uint(x);
    u += 0x1000u;
    u &= 0xFFFFE000u;
    return __uint_as_float(u);
}
__device__ __forceinline__ uint64_t tf32r2(uint64_t x) {
    uint32_t lo = (uint32_t)x, hi = (uint32_t)(x >> 32);
    lo = (lo + 0x1000u) & 0xFFFFE000u;
    hi = (hi + 0x1000u) & 0xFFFFE000u;
    return ((uint64_t)hi << 32) | lo;
}

__device__ __forceinline__ uint64_t fma2(uint64_t a, uint64_t b, uint64_t c) {
    uint64_t d; asm("fma.rn.f32x2 %0,%1,%2,%3;" : "=l"(d) : "l"(a), "l"(b), "l"(c)); return d;
}
__device__ __forceinline__ uint64_t mul2(uint64_t a, uint64_t b) {
    uint64_t d; asm("mul.rn.f32x2 %0,%1,%2;" : "=l"(d) : "l"(a), "l"(b)); return d;
}
__device__ __forceinline__ uint64_t add2(uint64_t a, uint64_t b) {
    uint64_t d; asm("add.rn.f32x2 %0,%1,%2;" : "=l"(d) : "l"(a), "l"(b)); return d;
}
__device__ __forceinline__ uint64_t sub2(uint64_t a, uint64_t b) {
    uint64_t d; asm("sub.rn.f32x2 %0,%1,%2;" : "=l"(d) : "l"(a), "l"(b)); return d;
}
__device__ __forceinline__ uint64_t pack2(float lo, float hi) {
    return ((uint64_t)__float_as_uint(hi) << 32) | (uint64_t)__float_as_uint(lo);
}

// ---------------------------------------------------------------------------
// Kernel A: blocks [0,2048) = edges tiles (exact R10 path); blocks
// [2048,3072) = scalar loss-main (R8 path). Loss blocks dispatch last,
// filling the edges tail wave. Whole kernel compiles to 32 regs (R8-proven).
// ---------------------------------------------------------------------------
__global__ void __launch_bounds__(512, 4) edges_loss_kernel(
    const float* __restrict__ pd,
    const int*   __restrict__ gt,
    const float* __restrict__ weight)
{
    __shared__ __align__(16) uint64_t s_patt[1440];   // 36*40
    __shared__ __align__(16) uint64_t s_v   [1440];   // 36*40
    __shared__ __align__(16) uint64_t s_b   [1296];   // 36*36
    __shared__ __align__(16) uint64_t s_mag [1156];   // 34*34 (dir in low bits)
    __shared__ uint8_t  s_gt[1600];                   // 40*40

    const int bid  = blockIdx.x;
    const int tid  = threadIdx.x;
    const int lane = tid & 31;

    if (bid >= EDGE_BLKS) {
        // -------------------- scalar loss-main (tail filler) ----------------
        const int lbid = bid - EDGE_BLKS;            // 0..1023
        float acc = 0.f;
        #pragma unroll 1
        for (int it = 0; it < 4; it++) {
            int p  = lbid * 2048 + it * 512 + tid;   // 0..2097151
            int b  = p >> 18;
            int hw = p & 262143;
            int g  = gt[p];
            const float* base = pd + (((size_t)b * CC) << 18) + hw;
            float vmax = -1e30f, vg = 0.f;
            float vals[CC];
            #pragma unroll
            for (int c = 0; c < CC; c++) {
                float v = base[(size_t)c << 18];
                vals[c] = v;
                if (c == g) vg = v;
                vmax = fmaxf(vmax, v);
            }
            float s = 0.f;
            #pragma unroll
            for (int c = 0; c < CC; c++) s += __expf(vals[c] - vmax);
            float lse = vmax + __logf(s);
            float t = weight[g] * (vg - lse);
            g_t[p] = t;
            acc += t;
        }
        #pragma unroll
        for (int off = 16; off > 0; off >>= 1)
            acc += __shfl_down_sync(0xffffffffu, acc, off);
        float* ws = (float*)s_patt;
        if (lane == 0) ws[tid >> 5] = acc;
        __syncthreads();
        if (tid == 0) {
            float t = 0.f;
            #pragma unroll
            for (int i = 0; i < 16; i++) t += ws[i];
            g_p1[lbid] = t;
        }
        return;
    }

    // ------------------------------ edges tile ------------------------------
    const int ex = bid & 15;
    const int ey = (bid >> 4) & 15;
    const int b  = bid >> 8;
    const int x0 = ex * 32;
    const int y0 = ey * 32;
    const bool interior = (ex != 0) && (ex != 15) && (ey != 0) && (ey != 15);

    const float G0 = tf32r(0.054488684549642945f);
    const float G1 = tf32r(0.244201342003233320f);
    const float G2 = tf32r(0.402619946894227900f);
    const uint64_t G0p = pack2(G0, G0), G1p = pack2(G1, G1), G2p = pack2(G2, G2);
    const uint64_t M2p = pack2(-2.f, -2.f), P2p = pack2(2.f, 2.f);
    const uint64_t Z2  = 0;
    const float TT = 0.41421356237309503f;

    float lutv;
    {
        float a0 = (float)( lane       & 1);
        float a1 = (float)((lane >> 1) & 1);
        float a2 = (float)((lane >> 2) & 1);
        float a3 = (float)((lane >> 3) & 1);
        float a4 = (float)((lane >> 4) & 1);
        float s = G0 * a0;
        s = fmaf(G1, a1, s);
        s = fmaf(G2, a2, s);
        s = fmaf(G1, a3, s);
        s = fmaf(G0, a4, s);
        lutv = tf32r(s);
    }

    for (int e = tid; e < 1600; e += 512) {
        int i = e / 40, j = e - 40*i;
        s_gt[e] = (uint8_t)gt[(b << 18) + (reflectI(y0-4+i) << 9) + reflectI(x0-4+j)];
    }
    __syncthreads();

    for (int e = tid; e < 1440; e += 512) {
        int i = e / 40, j = e - 40*i;
        uint64_t B = 0;
        #pragma unroll
        for (int k = 0; k < 5; k++) {
            int g = s_gt[(i+k)*40 + j];
            B |= 1ull << (5*g + k);
        }
        s_patt[e] = B;
    }
    __syncthreads();

    const int sb_i0 = tid / 34;
    const int sb_base0 = sb_i0*36 + (tid - 34*sb_i0) + 37;
    const int sb_i1 = (tid + 512) / 34;
    const int sb_base1 = sb_i1*36 + ((tid + 512) - 34*sb_i1) + 37;

    auto sobel_math = [&](uint64_t b00, uint64_t b01, uint64_t b02,
                          uint64_t b10, uint64_t b12,
                          uint64_t b20, uint64_t b21, uint64_t b22) -> uint64_t {
        uint64_t gxp = sub2(Z2, b00);
        gxp = add2(gxp, b02);
        gxp = fma2(M2p, b10, gxp);
        gxp = fma2(P2p, b12, gxp);
        gxp = sub2(gxp, b20);
        gxp = add2(gxp, b22);
        uint64_t gyp = sub2(Z2, b00);
        gyp = fma2(M2p, b01, gyp);
        gyp = sub2(gyp, b02);
        gyp = add2(gyp, b20);
        gyp = fma2(P2p, b21, gyp);
        gyp = add2(gyp, b22);

        float gx0 = __uint_as_float((uint32_t)gxp);
        float gx1 = __uint_as_float((uint32_t)(gxp >> 32));
        float gy0 = __uint_as_float((uint32_t)gyp);
        float gy1 = __uint_as_float((uint32_t)(gyp >> 32));

        float s20 = __fadd_rn(__fadd_rn(__fmul_rn(gx0,gx0), __fmul_rn(gy0,gy0)), 1e-6f);
        float s21 = __fadd_rn(__fadd_rn(__fmul_rn(gx1,gx1), __fmul_rn(gy1,gy1)), 1e-6f);
        float m0 = sqrtf(s20);
        float m1 = sqrtf(s21);
        float ax0 = fabsf(gx0), ay0 = fabsf(gy0);
        float ax1 = fabsf(gx1), ay1 = fabsf(gy1);
        uint32_t d0 = (ay0 <= TT*ax0) ? 0u
                    : (ax0 <= TT*ay0) ? 1u
                    : (((gx0 > 0.f) == (gy0 > 0.f)) ? 2u : 3u);
        uint32_t d1 = (ay1 <= TT*ax1) ? 0u
                    : (ax1 <= TT*ay1) ? 1u
                    : (((gx1 > 0.f) == (gy1 > 0.f)) ? 2u : 3u);
        uint32_t mb0 = (__float_as_uint(m0) & ~3u) | d0;
        uint32_t mb1 = (__float_as_uint(m1) & ~3u) | d1;
        return ((uint64_t)mb1 << 32) | mb0;
    };

    auto sobel_fast = [&](int e, int base) {
        s_mag[e] = sobel_math(s_b[base-37], s_b[base-36], s_b[base-35],
                              s_b[base-1],                s_b[base+1],
                              s_b[base+35], s_b[base+36], s_b[base+37]);
    };

    const int nw  = tid >> 5;
    const int nmj = lane + 1;

    #pragma unroll 1
    for (int c2 = 0; c2 < 6; c2++) {
        const int sh0 = 10*c2, sh1 = sh0 + 5;

        {
            uint64_t B = s_patt[tid];
            float v0 = __shfl_sync(0xffffffffu, lutv, (int)((B >> sh0) & 31));
            float v1 = __shfl_sync(0xffffffffu, lutv, (int)((B >> sh1) & 31));
            s_v[tid] = pack2(v0, v1);
            B = s_patt[tid + 512];
            v0 = __shfl_sync(0xffffffffu, lutv, (int)((B >> sh0) & 31));
            v1 = __shfl_sync(0xffffffffu, lutv, (int)((B >> sh1) & 31));
            s_v[tid + 512] = pack2(v0, v1);
            if (tid < 416) {                 // warps 0..12 fully active (shfl-safe)
                B = s_patt[tid + 1024];
                v0 = __shfl_sync(0xffffffffu, lutv, (int)((B >> sh0) & 31));
                v1 = __shfl_sync(0xffffffffu, lutv, (int)((B >> sh1) & 31));
                s_v[tid + 1024] = pack2(v0, v1);
            }
        }
        __syncthreads();

        for (int e = tid; e < 1296; e += 512) {
            int i = e / 36, j = e - 36*i;
            const uint64_t* row = s_v + i*40 + j;
            uint64_t s = mul2(G0p, row[0]);
            s = fma2(G1p, row[1], s);
            s = fma2(G2p, row[2], s);
            s = fma2(G1p, row[3], s);
            s = fma2(G0p, row[4], s);
            s_b[e] = tf32r2(s);
        }
        __syncthreads();

        if (interior) {
            sobel_fast(tid,       sb_base0);
            sobel_fast(tid + 512, sb_base1);
            if (tid < 132) {
                int e = tid + 1024;
                int i = e / 34;
                sobel_fast(e, i*36 + (e - 34*i) + 37);
            }
        } else {
            for (int e = tid; e < 1156; e += 512) {
                int i = e / 34, j = e - 34*i;
                int gy = y0 - 1 + i, gx = x0 - 1 + j;
                uint64_t magp = 0;
                if ((unsigned)gy < (unsigned)HH && (unsigned)gx < (unsigned)WWID) {
                    int am = (max(gy-1, 0)      - (y0 - 2)) * 36;
                    int a0 = (gy                - (y0 - 2)) * 36;
                    int ap = (min(gy+1, HH-1)   - (y0 - 2)) * 36;
                    int cm =  max(gx-1, 0)      - (x0 - 2);
                    int c0 =  gx                - (x0 - 2);
                    int cp =  min(gx+1, WWID-1) - (x0 - 2);
                    magp = sobel_math(s_b[am+cm], s_b[am+c0], s_b[am+cp],
                                      s_b[a0+cm],             s_b[a0+cp],
                                      s_b[ap+cm], s_b[ap+c0], s_b[ap+cp]);
                }
                s_mag[e] = magp;
            }
        }
        __syncthreads();

        {
            const float* magf = (const float*)s_mag;
            #pragma unroll
            for (int t = 0; t < 2; t++) {
                int r  = nw + t*16;
                int mi = r + 1;
                uint64_t mp = s_mag[mi*34 + nmj];
                unsigned sbits[2], wbits[2];
                #pragma unroll
                for (int l = 0; l < 2; l++) {
                    uint32_t mb = (uint32_t)(l ? (mp >> 32) : mp);
                    float m = __uint_as_float(mb);
                    int d = (int)(mb & 3u);
                    int dy = (d == 0) ? 0 : ((d == 2) ? -1 : 1);
                    int dx = (d == 1) ? 0 : 1;
                    float m1 = magf[((mi+dy)*34 + (nmj+dx))*2 + l];
                    float m2 = magf[((mi-dy)*34 + (nmj-dx))*2 + l];
                    float mr = tf32r(m);
                    int e2 = 0;
                    if (mr > tf32r(m1) && mr > tf32r(m2))
                        e2 = (m > 0.2f) ? 2 : ((m > 0.1f) ? 1 : 0);
                    sbits[l] = __ballot_sync(0xffffffffu, e2 == 2);
                    wbits[l] = __ballot_sync(0xffffffffu, e2 == 1);
                }
                if (lane == 0) {
                    int c = 2*c2;
                    int base0 = ((b*CC + c)*HH + y0 + r)*WPR + ex;
                    g_strong[base0] = sbits[0];
                    g_weak[base0]   = wbits[0];
                    if (c + 1 < CC) {
                        int base1 = base0 + HH*WPR;
                        g_strong[base1] = sbits[1];
                        g_weak[base1]   = wbits[1];
                    }
                }
            }
        }
        __syncthreads();
    }
}

// ---------------------------------------------------------------------------
// Kernel B: flood only (R10 flood path; no loss baggage -> low regs).
// ---------------------------------------------------------------------------
__global__ void __launch_bounds__(1024) flood_kernel()
{
    extern __shared__ uint32_t sh[];
    uint32_t* sS = sh;
    uint32_t* sW = sh + WPI;
    const int tid = threadIdx.x;

    const int img = blockIdx.x;
    const uint32_t* gs = g_strong + (size_t)img * WPI;
    const uint32_t* gw = g_weak   + (size_t)img * WPI;

    for (int i = tid; i < WPI; i += 1024) {
        uint32_t s = gs[i];
        sS[i] = s;
        sW[i] = gw[i] & ~s;
    }
    __syncthreads();

    const int col = tid & 15;
    const int r0  = (tid >> 4) * 8;

    for (;;) {
        bool ch = false;
        #pragma unroll
        for (int pass = 0; pass < 2; pass++) {
            for (int kk = 0; kk < 8; kk++) {
                int k = pass ? 7 - kk : kk;
                int r = r0 + k;
                int i = r * WPR + col;
                uint32_t w = sW[i];
                if (!w) continue;
                uint32_t ext = 0;
                if (r > 0)     ext |= sS[i - WPR];
                if (r < HH-1)  ext |= sS[i + WPR];
                uint32_t side = 0;
                if (col > 0) {
                    uint32_t lo = sS[i-1];
                    if (r > 0)    lo |= sS[i-1-WPR];
                    if (r < HH-1) lo |= sS[i-1+WPR];
                    side |= lo >> 31;
                }
                if (col < WPR-1) {
                    uint32_t hi = sS[i+1];
                    if (r > 0)    hi |= sS[i+1-WPR];
                    if (r < HH-1) hi |= sS[i+1+WPR];
                    side |= hi << 31;
                }
                uint32_t cur = sS[i];
                bool lch = false;
                for (;;) {
                    uint32_t o = cur | ext;
                    uint32_t d = o | (o << 1) | (o >> 1) | side;
                    uint32_t cand = d & w;
                    if (!cand) break;
                    cur |= cand; w &= ~cand; lch = true;
                }
                if (lch) { sS[i] = cur; sW[i] = w; ch = true; }
            }
        }
        if (!__syncthreads_or((int)ch)) break;
    }

    uint32_t* gd = g_dil + (size_t)img * WPI;
    #pragma unroll
    for (int k = 0; k < 8; k++) {
        int r = r0 + k;
        int i = r * WPR + col;
        uint32_t s = sS[i];
        uint32_t d = s | (s << 1) | (s >> 1);
        if (r > 0)       d |= sS[i - WPR];
        if (r < HH-1)    d |= sS[i + WPR];
        if (col > 0)     d |= sS[i-1] >> 31;
        if (col < WPR-1) d |= sS[i+1] << 31;
        gd[i] = d;
    }
}

// ---------------------------------------------------------------------------
// Kernel C: loss edge correction S2 + fused final reduction.
// ---------------------------------------------------------------------------
__global__ void __launch_bounds__(256) loss_edge_kernel(const int* __restrict__ gt,
                                                        float* __restrict__ out)
{
    const int q  = blockIdx.x * 256 + threadIdx.x;
    const int b  = q >> 16;
    const int hw = (q & 65535) << 2;
    const int widx = hw >> 5;

    const int4   g4 = ((const int4*)gt)[q];
    const float4 t4 = ((const float4*)g_t)[q];

    float s2 = 0.f;
    const int   gs[4] = {g4.x, g4.y, g4.z, g4.w};
    const float ts[4] = {t4.x, t4.y, t4.z, t4.w};
    #pragma unroll
    for (int j = 0; j < 4; j++) {
        uint32_t bits = g_dil[(size_t)(b * CC + gs[j]) * WPI + widx];
        if ((bits >> ((hw + j) & 31)) & 1u) s2 += ts[j];
    }

    #pragma unroll
    for (int off = 16; off > 0; off >>= 1)
        s2 += __shfl_down_sync(0xffffffffu, s2, off);
    __shared__ float ws[8];
    if ((threadIdx.x & 31) == 0) ws[threadIdx.x >> 5] = s2;
    __syncthreads();
    __shared__ bool isLast;
    if (threadIdx.x == 0) {
        float t = 0.f;
        #pragma unroll
        for (int i = 0; i < 8; i++) t += ws[i];
        g_p2[blockIdx.x] = t;
        __threadfence();
        unsigned v = atomicAdd(&g_count, 1u);
        isLast = (v == NLOSS2 - 1);
    }
    __syncthreads();

    if (isLast) {
        __shared__ double red[256];
        double a = 0.0;
        for (int i = threadIdx.x; i < NLOSS1; i += 256) a += (double)g_p1[i];
        for (int i = threadIdx.x; i < NLOSS2; i += 256) a += 2.0 * (double)g_p2[i];
        red[threadIdx.x] = a;
        __syncthreads();
        for (int s = 128; s > 0; s >>= 1) {
            if (threadIdx.x < s) red[threadIdx.x] += red[threadIdx.x + s];
            __syncthreads();
        }
        if (threadIdx.x == 0) {
            out[0] = (float)(-red[0] / 2097152.0);
            g_count = 0;
        }
    }
}

// ---------------------------------------------------------------------------
extern "C" void kernel_launch(void* const* d_in, const int* in_sizes, int n_in,
                              void* d_out, int out_size)
{
    (void)in_sizes; (void)n_in; (void)out_size;
    const float* pd     = (const float*)d_in[0];
    const int*   gt     = (const int*)  d_in[1];
    const float* weight = (const float*)d_in[2];
    float* out = (float*)d_out;

    cudaFuncSetAttribute(flood_kernel,
                         cudaFuncAttributeMaxDynamicSharedMemorySize, 2 * WPI * 4);

    edges_loss_kernel<<<EDGE_BLKS + NLOSS1, 512>>>(pd, gt, weight);
    flood_kernel<<<NIMG, 1024, 2 * WPI * 4>>>();
    loss_edge_kernel<<<NLOSS2, 256>>>(gt, out);
}

// round 16
// speedup vs baseline: 1.1358x; 1.0336x over previous
#include <cuda_runtime.h>
#include <stdint.h>

#define BB   8
#define CC   11
#define HH   512
#define WWID 512
#define NIMG (BB*CC)        // 88
#define WPR  16             // 32-bit words per row (512/32)
#define WPI  (HH*WPR)       // words per image = 8192
#define EDGE_BLKS 2048
#define NLOSS1 1024         // scalar loss-main blocks (in kernel A tail)
#define NLOSS2 512          // loss-edge blocks (64 per batch, in kernel B)

// scratch (static __device__ — no allocations)
__device__ uint32_t g_strong[NIMG*WPI];
__device__ uint32_t g_weak  [NIMG*WPI];
__device__ uint32_t g_dil   [NIMG*WPI];
__device__ float    g_t     [BB*HH*WWID];
__device__ float    g_p1[NLOSS1];
__device__ float    g_p2[NLOSS2];
__device__ unsigned batch_done[BB];
__device__ unsigned le_count = 0;

__device__ __forceinline__ int reflectI(int r) {
    r = (r < 0) ? -r : r;
    return (r > HH-1) ? (2*(HH-1) - r) : r;
}

__device__ __forceinline__ float tf32r(float x) {
    uint32_t u = __float_as_uint(x);
    u += 0x1000u;
    u &= 0xFFFFE000u;
    return __uint_as_float(u);
}
__device__ __forceinline__ uint64_t tf32r2(uint64_t x) {
    uint32_t lo = (uint32_t)x, hi = (uint32_t)(x >> 32);
    lo = (lo + 0x1000u) & 0xFFFFE000u;
    hi = (hi + 0x1000u) & 0xFFFFE000u;
    return ((uint64_t)hi << 32) | lo;
}

__device__ __forceinline__ uint64_t fma2(uint64_t a, uint64_t b, uint64_t c) {
    uint64_t d; asm("fma.rn.f32x2 %0,%1,%2,%3;" : "=l"(d) : "l"(a), "l"(b), "l"(c)); return d;
}
__device__ __forceinline__ uint64_t mul2(uint64_t a, uint64_t b) {
    uint64_t d; asm("mul.rn.f32x2 %0,%1,%2;" : "=l"(d) : "l"(a), "l"(b)); return d;
}
__device__ __forceinline__ uint64_t add2(uint64_t a, uint64_t b) {
    uint64_t d; asm("add.rn.f32x2 %0,%1,%2;" : "=l"(d) : "l"(a), "l"(b)); return d;
}
__device__ __forceinline__ uint64_t sub2(uint64_t a, uint64_t b) {
    uint64_t d; asm("sub.rn.f32x2 %0,%1,%2;" : "=l"(d) : "l"(a), "l"(b)); return d;
}
__device__ __forceinline__ uint64_t pack2(float lo, float hi) {
    return ((uint64_t)__float_as_uint(hi) << 32) | (uint64_t)__float_as_uint(lo);
}

// ---------------------------------------------------------------------------
// Kernel A: blocks [0,2048) = edges tiles (R10 path); blocks [2048,3072) =
// scalar loss-main (tail filler). Unchanged from R15 (146.6us, 32 regs).
// ---------------------------------------------------------------------------
__global__ void __launch_bounds__(512, 4) edges_loss_kernel(
    const float* __restrict__ pd,
    const int*   __restrict__ gt,
    const float* __restrict__ weight)
{
    __shared__ __align__(16) uint64_t s_patt[1440];   // 36*40
    __shared__ __align__(16) uint64_t s_v   [1440];   // 36*40
    __shared__ __align__(16) uint64_t s_b   [1296];   // 36*36
    __shared__ __align__(16) uint64_t s_mag [1156];   // 34*34 (dir in low bits)
    __shared__ uint8_t  s_gt[1600];                   // 40*40

    const int bid  = blockIdx.x;
    const int tid  = threadIdx.x;
    const int lane = tid & 31;

    if (bid >= EDGE_BLKS) {
        // -------------------- scalar loss-main (tail filler) ----------------
        const int lbid = bid - EDGE_BLKS;            // 0..1023
        float acc = 0.f;
        #pragma unroll 1
        for (int it = 0; it < 4; it++) {
            int p  = lbid * 2048 + it * 512 + tid;   // 0..2097151
            int b  = p >> 18;
            int hw = p & 262143;
            int g  = gt[p];
            const float* base = pd + (((size_t)b * CC) << 18) + hw;
            float vmax = -1e30f, vg = 0.f;
            float vals[CC];
            #pragma unroll
            for (int c = 0; c < CC; c++) {
                float v = base[(size_t)c << 18];
                vals[c] = v;
                if (c == g) vg = v;
                vmax = fmaxf(vmax, v);
            }
            float s = 0.f;
            #pragma unroll
            for (int c = 0; c < CC; c++) s += __expf(vals[c] - vmax);
            float lse = vmax + __logf(s);
            float t = weight[g] * (vg - lse);
            g_t[p] = t;
            acc += t;
        }
        #pragma unroll
        for (int off = 16; off > 0; off >>= 1)
            acc += __shfl_down_sync(0xffffffffu, acc, off);
        float* ws = (float*)s_patt;
        if (lane == 0) ws[tid >> 5] = acc;
        __syncthreads();
        if (tid == 0) {
            float t = 0.f;
            #pragma unroll
            for (int i = 0; i < 16; i++) t += ws[i];
            g_p1[lbid] = t;
        }
        return;
    }

    // ------------------------------ edges tile ------------------------------
    const int ex = bid & 15;
    const int ey = (bid >> 4) & 15;
    const int b  = bid >> 8;
    const int x0 = ex * 32;
    const int y0 = ey * 32;
    const bool interior = (ex != 0) && (ex != 15) && (ey != 0) && (ey != 15);

    const float G0 = tf32r(0.054488684549642945f);
    const float G1 = tf32r(0.244201342003233320f);
    const float G2 = tf32r(0.402619946894227900f);
    const uint64_t G0p = pack2(G0, G0), G1p = pack2(G1, G1), G2p = pack2(G2, G2);
    const uint64_t M2p = pack2(-2.f, -2.f), P2p = pack2(2.f, 2.f);
    const uint64_t Z2  = 0;
    const float TT = 0.41421356237309503f;

    float lutv;
    {
        float a0 = (float)( lane       & 1);
        float a1 = (float)((lane >> 1) & 1);
        float a2 = (float)((lane >> 2) & 1);
        float a3 = (float)((lane >> 3) & 1);
        float a4 = (float)((lane >> 4) & 1);
        float s = G0 * a0;
        s = fmaf(G1, a1, s);
        s = fmaf(G2, a2, s);
        s = fmaf(G1, a3, s);
        s = fmaf(G0, a4, s);
        lutv = tf32r(s);
    }

    for (int e = tid; e < 1600; e += 512) {
        int i = e / 40, j = e - 40*i;
        s_gt[e] = (uint8_t)gt[(b << 18) + (reflectI(y0-4+i) << 9) + reflectI(x0-4+j)];
    }
    __syncthreads();

    for (int e = tid; e < 1440; e += 512) {
        int i = e / 40, j = e - 40*i;
        uint64_t B = 0;
        #pragma unroll
        for (int k = 0; k < 5; k++) {
            int g = s_gt[(i+k)*40 + j];
            B |= 1ull << (5*g + k);
        }
        s_patt[e] = B;
    }
    __syncthreads();

    const int sb_i0 = tid / 34;
    const int sb_base0 = sb_i0*36 + (tid - 34*sb_i0) + 37;
    const int sb_i1 = (tid + 512) / 34;
    const int sb_base1 = sb_i1*36 + ((tid + 512) - 34*sb_i1) + 37;

    auto sobel_math = [&](uint64_t b00, uint64_t b01, uint64_t b02,
                          uint64_t b10, uint64_t b12,
                          uint64_t b20, uint64_t b21, uint64_t b22) -> uint64_t {
        uint64_t gxp = sub2(Z2, b00);
        gxp = add2(gxp, b02);
        gxp = fma2(M2p, b10, gxp);
        gxp = fma2(P2p, b12, gxp);
        gxp = sub2(gxp, b20);
        gxp = add2(gxp, b22);
        uint64_t gyp = sub2(Z2, b00);
        gyp = fma2(M2p, b01, gyp);
        gyp = sub2(gyp, b02);
        gyp = add2(gyp, b20);
        gyp = fma2(P2p, b21, gyp);
        gyp = add2(gyp, b22);

        float gx0 = __uint_as_float((uint32_t)gxp);
        float gx1 = __uint_as_float((uint32_t)(gxp >> 32));
        float gy0 = __uint_as_float((uint32_t)gyp);
        float gy1 = __uint_as_float((uint32_t)(gyp >> 32));

        float s20 = __fadd_rn(__fadd_rn(__fmul_rn(gx0,gx0), __fmul_rn(gy0,gy0)), 1e-6f);
        float s21 = __fadd_rn(__fadd_rn(__fmul_rn(gx1,gx1), __fmul_rn(gy1,gy1)), 1e-6f);
        float m0 = sqrtf(s20);
        float m1 = sqrtf(s21);
        float ax0 = fabsf(gx0), ay0 = fabsf(gy0);
        float ax1 = fabsf(gx1), ay1 = fabsf(gy1);
        uint32_t d0 = (ay0 <= TT*ax0) ? 0u
                    : (ax0 <= TT*ay0) ? 1u
                    : (((gx0 > 0.f) == (gy0 > 0.f)) ? 2u : 3u);
        uint32_t d1 = (ay1 <= TT*ax1) ? 0u
                    : (ax1 <= TT*ay1) ? 1u
                    : (((gx1 > 0.f) == (gy1 > 0.f)) ? 2u : 3u);
        uint32_t mb0 = (__float_as_uint(m0) & ~3u) | d0;
        uint32_t mb1 = (__float_as_uint(m1) & ~3u) | d1;
        return ((uint64_t)mb1 << 32) | mb0;
    };

    auto sobel_fast = [&](int e, int base) {
        s_mag[e] = sobel_math(s_b[base-37], s_b[base-36], s_b[base-35],
                              s_b[base-1],                s_b[base+1],
                              s_b[base+35], s_b[base+36], s_b[base+37]);
    };

    const int nw  = tid >> 5;
    const int nmj = lane + 1;

    #pragma unroll 1
    for (int c2 = 0; c2 < 6; c2++) {
        const int sh0 = 10*c2, sh1 = sh0 + 5;

        {
            uint64_t B = s_patt[tid];
            float v0 = __shfl_sync(0xffffffffu, lutv, (int)((B >> sh0) & 31));
            float v1 = __shfl_sync(0xffffffffu, lutv, (int)((B >> sh1) & 31));
            s_v[tid] = pack2(v0, v1);
            B = s_patt[tid + 512];
            v0 = __shfl_sync(0xffffffffu, lutv, (int)((B >> sh0) & 31));
            v1 = __shfl_sync(0xffffffffu, lutv, (int)((B >> sh1) & 31));
            s_v[tid + 512] = pack2(v0, v1);
            if (tid < 416) {                 // warps 0..12 fully active (shfl-safe)
                B = s_patt[tid + 1024];
                v0 = __shfl_sync(0xffffffffu, lutv, (int)((B >> sh0) & 31));
                v1 = __shfl_sync(0xffffffffu, lutv, (int)((B >> sh1) & 31));
                s_v[tid + 1024] = pack2(v0, v1);
            }
        }
        __syncthreads();

        for (int e = tid; e < 1296; e += 512) {
            int i = e / 36, j = e - 36*i;
            const uint64_t* row = s_v + i*40 + j;
            uint64_t s = mul2(G0p, row[0]);
            s = fma2(G1p, row[1], s);
            s = fma2(G2p, row[2], s);
            s = fma2(G1p, row[3], s);
            s = fma2(G0p, row[4], s);
            s_b[e] = tf32r2(s);
        }
        __syncthreads();

        if (interior) {
            sobel_fast(tid,       sb_base0);
            sobel_fast(tid + 512, sb_base1);
            if (tid < 132) {
                int e = tid + 1024;
                int i = e / 34;
                sobel_fast(e, i*36 + (e - 34*i) + 37);
            }
        } else {
            for (int e = tid; e < 1156; e += 512) {
                int i = e / 34, j = e - 34*i;
                int gy = y0 - 1 + i, gx = x0 - 1 + j;
                uint64_t magp = 0;
                if ((unsigned)gy < (unsigned)HH && (unsigned)gx < (unsigned)WWID) {
                    int am = (max(gy-1, 0)      - (y0 - 2)) * 36;
                    int a0 = (gy                - (y0 - 2)) * 36;
                    int ap = (min(gy+1, HH-1)   - (y0 - 2)) * 36;
                    int cm =  max(gx-1, 0)      - (x0 - 2);
                    int c0 =  gx                - (x0 - 2);
                    int cp =  min(gx+1, WWID-1) - (x0 - 2);
                    magp = sobel_math(s_b[am+cm], s_b[am+c0], s_b[am+cp],
                                      s_b[a0+cm],             s_b[a0+cp],
                                      s_b[ap+cm], s_b[ap+c0], s_b[ap+cp]);
                }
                s_mag[e] = magp;
            }
        }
        __syncthreads();

        {
            const float* magf = (const float*)s_mag;
            #pragma unroll
            for (int t = 0; t < 2; t++) {
                int r  = nw + t*16;
                int mi = r + 1;
                uint64_t mp = s_mag[mi*34 + nmj];
                unsigned sbits[2], wbits[2];
                #pragma unroll
                for (int l = 0; l < 2; l++) {
                    uint32_t mb = (uint32_t)(l ? (mp >> 32) : mp);
                    float m = __uint_as_float(mb);
                    int d = (int)(mb & 3u);
                    int dy = (d == 0) ? 0 : ((d == 2) ? -1 : 1);
                    int dx = (d == 1) ? 0 : 1;
                    float m1 = magf[((mi+dy)*34 + (nmj+dx))*2 + l];
                    float m2 = magf[((mi-dy)*34 + (nmj-dx))*2 + l];
                    float mr = tf32r(m);
                    int e2 = 0;
                    if (mr > tf32r(m1) && mr > tf32r(m2))
                        e2 = (m > 0.2f) ? 2 : ((m > 0.1f) ? 1 : 0);
                    sbits[l] = __ballot_sync(0xffffffffu, e2 == 2);
                    wbits[l] = __ballot_sync(0xffffffffu, e2 == 1);
                }
                if (lane == 0) {
                    int c = 2*c2;
                    int base0 = ((b*CC + c)*HH + y0 + r)*WPR + ex;
                    g_strong[base0] = sbits[0];
                    g_weak[base0]   = wbits[0];
                    if (c + 1 < CC) {
                        int base1 = base0 + HH*WPR;
                        g_strong[base1] = sbits[1];
                        g_weak[base1]   = wbits[1];
                    }
                }
            }
        }
        __syncthreads();
    }
}

// ---------------------------------------------------------------------------
// Kernel B: blocks [0,88) = flood (R10 path, signals batch_done[b]);
// blocks [88,600) = loss-edge, spinning on per-batch flood completion.
// Dispatch order guarantees flood blocks get slots first -> deadlock-free.
// ---------------------------------------------------------------------------
__global__ void __launch_bounds__(1024) flood_lossedge_kernel(
    const int* __restrict__ gt,
    float* __restrict__ out)
{
    extern __shared__ uint32_t sh[];
    const int tid = threadIdx.x;
    const int lane = tid & 31;

    if (blockIdx.x < NIMG) {
        // ------------------------------- flood ------------------------------
        uint32_t* sS = sh;
        uint32_t* sW = sh + WPI;

        const int img = blockIdx.x;
        const uint32_t* gs = g_strong + (size_t)img * WPI;
        const uint32_t* gw = g_weak   + (size_t)img * WPI;

        for (int i = tid; i < WPI; i += 1024) {
            uint32_t s = gs[i];
            sS[i] = s;
            sW[i] = gw[i] & ~s;
        }
        __syncthreads();

        const int col = tid & 15;
        const int r0  = (tid >> 4) * 8;

        for (;;) {
            bool ch = false;
            #pragma unroll
            for (int pass = 0; pass < 2; pass++) {
                for (int kk = 0; kk < 8; kk++) {
                    int k = pass ? 7 - kk : kk;
                    int r = r0 + k;
                    int i = r * WPR + col;
                    uint32_t w = sW[i];
                    if (!w) continue;
                    uint32_t ext = 0;
                    if (r > 0)     ext |= sS[i - WPR];
                    if (r < HH-1)  ext |= sS[i + WPR];
                    uint32_t side = 0;
                    if (col > 0) {
                        uint32_t lo = sS[i-1];
                        if (r > 0)    lo |= sS[i-1-WPR];
                        if (r < HH-1) lo |= sS[i-1+WPR];
                        side |= lo >> 31;
                    }
                    if (col < WPR-1) {
                        uint32_t hi = sS[i+1];
                        if (r > 0)    hi |= sS[i+1-WPR];
                        if (r < HH-1) hi |= sS[i+1+WPR];
                        side |= hi << 31;
                    }
                    uint32_t cur = sS[i];
                    bool lch = false;
                    for (;;) {
                        uint32_t o = cur | ext;
                        uint32_t d = o | (o << 1) | (o >> 1) | side;
                        uint32_t cand = d & w;
                        if (!cand) break;
                        cur |= cand; w &= ~cand; lch = true;
                    }
                    if (lch) { sS[i] = cur; sW[i] = w; ch = true; }
                }
            }
            if (!__syncthreads_or((int)ch)) break;
        }

        uint32_t* gd = g_dil + (size_t)img * WPI;
        #pragma unroll
        for (int k = 0; k < 8; k++) {
            int r = r0 + k;
            int i = r * WPR + col;
            uint32_t s = sS[i];
            uint32_t d = s | (s << 1) | (s >> 1);
            if (r > 0)       d |= sS[i - WPR];
            if (r < HH-1)    d |= sS[i + WPR];
            if (col > 0)     d |= sS[i-1] >> 31;
            if (col < WPR-1) d |= sS[i+1] << 31;
            gd[i] = d;
        }

        __threadfence();
        __syncthreads();
        if (tid == 0) atomicAdd(&batch_done[img / CC], 1u);
        return;
    }

    // ----------------------- loss-edge (per-batch spin) ---------------------
    const int lbid  = blockIdx.x - NIMG;        // 0..511
    const int batch = lbid >> 6;                // 64 blocks per batch
    const int chunk = lbid & 63;

    if (tid == 0) {
        while (atomicAdd(&batch_done[batch], 0u) < (unsigned)CC) __nanosleep(64);
    }
    __syncthreads();

    // 1024 quads per block (1 per thread)
    const int q  = batch * 65536 + chunk * 1024 + tid;
    const int hw = (q & 65535) << 2;
    const int widx = hw >> 5;

    const int4   g4 = ((const int4*)gt)[q];
    const float4 t4 = ((const float4*)g_t)[q];

    float s2 = 0.f;
    const int   gsx[4] = {g4.x, g4.y, g4.z, g4.w};
    const float tsx[4] = {t4.x, t4.y, t4.z, t4.w};
    #pragma unroll
    for (int j = 0; j < 4; j++) {
        uint32_t bits = g_dil[(size_t)(batch * CC + gsx[j]) * WPI + widx];
        if ((bits >> ((hw + j) & 31)) & 1u) s2 += tsx[j];
    }

    #pragma unroll
    for (int off = 16; off > 0; off >>= 1)
        s2 += __shfl_down_sync(0xffffffffu, s2, off);
    float* ws = (float*)sh;
    if (lane == 0) ws[tid >> 5] = s2;
    __syncthreads();
    __shared__ bool isLast;
    if (tid == 0) {
        float t = 0.f;
        #pragma unroll
        for (int i = 0; i < 32; i++) t += ws[i];
        g_p2[lbid] = t;
        __threadfence();
        unsigned v = atomicAdd(&le_count, 1u);
        isLast = (v == NLOSS2 - 1);
    }
    __syncthreads();

    if (isLast) {
        double a = 0.0;
        for (int i = tid; i < NLOSS1; i += 1024) a += (double)g_p1[i];
        for (int i = tid; i < NLOSS2; i += 1024) a += 2.0 * (double)g_p2[i];
        #pragma unroll
        for (int off = 16; off > 0; off >>= 1)
            a += __shfl_down_sync(0xffffffffu, a, off);
        double* wd = (double*)sh;
        if (lane == 0) wd[tid >> 5] = a;
        __syncthreads();
        if (tid == 0) {
            double t = 0.0;
            #pragma unroll
            for (int i = 0; i < 32; i++) t += wd[i];
            out[0] = (float)(-t / 2097152.0);
            // reset for next graph replay
            #pragma unroll
            for (int i = 0; i < BB; i++) batch_done[i] = 0;
            le_count = 0;
        }
    }
}

// ---------------------------------------------------------------------------
extern "C" void kernel_launch(void* const* d_in, const int* in_sizes, int n_in,
                              void* d_out, int out_size)
{
    (void)in_sizes; (void)n_in; (void)out_size;
    const float* pd     = (const float*)d_in[0];
    const int*   gt     = (const int*)  d_in[1];
    const float* weight = (const float*)d_in[2];
    float* out = (float*)d_out;

    cudaFuncSetAttribute(flood_lossedge_kernel,
                         cudaFuncAttributeMaxDynamicSharedMemorySize, 2 * WPI * 4);

    edges_loss_kernel<<<EDGE_BLKS + NLOSS1, 512>>>(pd, gt, weight);
    flood_lossedge_kernel<<<NIMG + NLOSS2, 1024, 2 * WPI * 4>>>(gt, out);
}